// round 10
// baseline (speedup 1.0000x reference)
#include <cuda_runtime.h>
#include <math.h>

#define N 8192
#define D 1024
#define GRIDN 444     // 3 blocks/SM on 148 SMs; co-residency guaranteed (smem allows 6/SM)

// Scratch (allocation-free rule: __device__ globals)
__device__ float g_a[N];            // sigmoid(x @ w)
__device__ int4  g_pack[N];         // {idx, bits(m), bits(c), 0} per column
__device__ int   g_rowstart[N + 2]; // lower_bound(idx >= j), j in [0, N+1]

// Persistent-kernel sync state (zero-init; reset by last block each replay)
__device__ volatile unsigned g_arrive = 0;  // phase-1 completion counter
__device__ volatile unsigned g_scanned = 0; // scan-done flag
__device__ unsigned g_done = 0;             // exit counter for reset

// ---------------------------------------------------------------------------
// Fused kernel: logits -> (barrier) -> scan (block 0) -> (flag) -> gather.
// All arithmetic is expression-identical to the validated R9 kernels, and
// each element's computation is independent of thread mapping, so g_a, pack,
// rowstart and the output are bitwise unchanged.
// ---------------------------------------------------------------------------
__global__ void __launch_bounds__(256, 3) k_fused(const float* __restrict__ x,
                                                  const float* __restrict__ w,
                                                  float* __restrict__ out) {
    __shared__ float sh[8192];      // scan tree (block 0); 32 KB
    __shared__ int s_last;

    const int tid  = threadIdx.x;
    const int bid  = blockIdx.x;
    const int warp = tid >> 5;
    const int lane = tid & 31;

    // ======================= Phase 1: logits =================================
    const float4* w4 = reinterpret_cast<const float4*>(w);
    for (int ch = bid; ch < N / 8; ch += GRIDN) {
        const int row = ch * 8 + warp;
        const float4* xr = reinterpret_cast<const float4*>(x) + (size_t)row * (D / 4);

        float4 xv[8];
#pragma unroll
        for (int k = 0; k < 8; k++)
            xv[k] = xr[lane + 32 * k];

        float s = 0.f;
#pragma unroll
        for (int k = 0; k < 8; k++) {
            const float4 wv = __ldg(&w4[lane + 32 * k]);
            s += xv[k].x * wv.x;
            s += xv[k].y * wv.y;
            s += xv[k].z * wv.z;
            s += xv[k].w * wv.w;
        }
#pragma unroll
        for (int off = 16; off; off >>= 1)
            s += __shfl_xor_sync(0xffffffffu, s, off);

        if (lane == 0) {
            float z = s, a;
            if (z >= 0.f) {
                a = 1.f / (1.f + expf(-z));
            } else {
                float e = expf(z);
                a = e / (1.f + e);
            }
            g_a[row] = a;
        }
    }

    // ================== Barrier: arrive; block 0 waits =======================
    __syncthreads();
    if (tid == 0) {
        __threadfence();
        atomicAdd((unsigned*)&g_arrive, 1u);
    }

    if (bid == 0) {
        // ---------------- Phase 2: scan (block 0 only) -----------------------
        if (tid == 0) {
            while (g_arrive < GRIDN) { }
            __threadfence();
        }
        __syncthreads();

        for (int i = tid; i < 4096; i += 256)
            sh[i] = g_a[2 * i] + g_a[2 * i + 1];
        __syncthreads();
        for (int l = 2; l <= 7; l++) {                 // n = 2048 .. 64
            const int n    = N >> l;
            const int off  = 8192 - 2 * (8192 >> l);
            const int offp = 8192 - 2 * (8192 >> (l - 1));
            for (int i = tid; i < n; i += 256)
                sh[off + i] = sh[offp + 2 * i] + sh[offp + 2 * i + 1];
            __syncthreads();
        }

        if (tid < 32) {
            for (int l = 8; l <= 13; l++) {
                const int n    = N >> l;
                const int off  = 8192 - 2 * (8192 >> l);
                const int offp = 8192 - 2 * (8192 >> (l - 1));
                if (tid < n)
                    sh[off + tid] = sh[offp + 2 * tid] + sh[offp + 2 * tid + 1];
                __syncwarp();
            }
            for (int l = 12; l >= 8; l--) {
                const int n    = N >> l;
                const int off  = 8192 - 2 * (8192 >> l);
                const int offc = 8192 - 2 * (8192 >> (l + 1));
                float v = 0.f;
                if (tid < n) {
                    if (tid & 1)       v = sh[offc + (tid >> 1)];
                    else if (tid == 0) v = sh[off];
                    else               v = sh[offc + (tid >> 1) - 1] + sh[off + tid];
                }
                __syncwarp();
                if (tid < n) sh[off + tid] = v;
                __syncwarp();
            }
        }
        __syncthreads();

        for (int l = 7; l >= 1; l--) {                 // n = 64 .. 4096
            const int n    = N >> l;
            const int off  = 8192 - 2 * (8192 >> l);
            const int offc = 8192 - 2 * (8192 >> (l + 1));
            for (int i = tid; i < n; i += 256) {
                float v;
                if (i & 1)       v = sh[offc + (i >> 1)];
                else if (i == 0) v = sh[off];
                else             v = sh[offc + (i >> 1) - 1] + sh[off + i];
                sh[off + i] = v;
            }
            __syncthreads();
        }

        for (int i = tid; i < N; i += 256) {
            const float ai = g_a[i];
            float bi;
            if (i == 0)      bi = ai;
            else if (i & 1)  bi = sh[i >> 1];
            else             bi = sh[(i >> 1) - 1] + ai;

            int prev;
            if (i == 0) {
                prev = 0;
            } else {
                const int k = i - 1;
                float bp;
                if (k == 0)      bp = g_a[0];
                else if (k & 1)  bp = sh[k >> 1];
                else             bp = sh[(k >> 1) - 1] + g_a[k];
                prev = (int)floorf(bp);
            }
            const int idx   = (int)floorf(bi);
            const bool same = (idx == prev);
            const float frac = bi - (float)idx;

            const float m = same ? ai : frac;
            const float c = same ? 0.f : (ai - frac);
            g_pack[i] = make_int4(idx, __float_as_int(m), __float_as_int(c), 0);

            if (i == 0) g_rowstart[0] = 0;
            else if (!same) g_rowstart[idx] = i;
            if (i == N - 1) s_last = idx;
        }
        __syncthreads();

        for (int j = s_last + 1 + tid; j <= N + 1; j += 256)
            g_rowstart[j] = N;
        __syncthreads();

        if (tid == 0) {
            __threadfence();
            atomicExch((unsigned*)&g_scanned, 1u);
        }
        __syncthreads();
    } else {
        // Other blocks: wait only for the scan flag.
        if (tid == 0) {
            while (g_scanned == 0) { }
            __threadfence();
        }
        __syncthreads();
    }

    // ======================= Phase 3: gather =================================
    for (int j = bid; j < N; j += GRIDN) {
        const int s = __ldg(&g_rowstart[j]);
        const int e = __ldg(&g_rowstart[j + 2]);

        float4 acc = make_float4(0.f, 0.f, 0.f, 0.f);
        for (int base = s; base < e; base += 32) {
            float wl = 0.f;
            const int i = base + lane;
            if (i < e) {
                const int4 p = __ldg(&g_pack[i]);
                if (p.x == j)          wl = __int_as_float(p.y);   // m
                else if (p.x == j + 1) wl = __int_as_float(p.z);   // c
            }
            const int cnt = min(32, e - base);
#pragma unroll 4
            for (int k = 0; k < cnt; k++) {
                const float wk = __shfl_sync(0xffffffffu, wl, k);
                if (fabsf(wk) > 1e-12f) {   // warp-uniform; sub-tolerance skip
                    const float4 v =
                        reinterpret_cast<const float4*>(x)[(size_t)(base + k) * (D / 4) + tid];
                    acc.x += wk * v.x;
                    acc.y += wk * v.y;
                    acc.z += wk * v.z;
                    acc.w += wk * v.w;
                }
            }
        }
        reinterpret_cast<float4*>(out)[(size_t)j * (D / 4) + tid] = acc;
    }

    // ============== Reset sync state for the next graph replay ===============
    __syncthreads();
    if (tid == 0) {
        __threadfence();
        const unsigned d = atomicAdd(&g_done, 1u);
        if (d == GRIDN - 1) {          // last block out resets everything
            g_arrive  = 0;
            g_scanned = 0;
            __threadfence();
            g_done = 0;
        }
    }
}

// ---------------------------------------------------------------------------
extern "C" void kernel_launch(void* const* d_in, const int* in_sizes, int n_in,
                              void* d_out, int out_size) {
    const float* x = (const float*)d_in[0];   // [8192, 1024] f32
    const float* w = (const float*)d_in[1];   // [1024, 1]    f32
    float* out = (float*)d_out;               // [8192, 1024] f32

    k_fused<<<GRIDN, 256>>>(x, w, out);
}

// round 11
// speedup vs baseline: 1.5390x; 1.5390x over previous
#include <cuda_runtime.h>
#include <math.h>

#define N 8192
#define D 1024

// Scratch (allocation-free rule: __device__ globals)
__device__ float g_a[N];            // sigmoid(x @ w)
__device__ int4  g_pack[N];         // {idx, bits(m), bits(c), 0} per column
__device__ int   g_rowstart[N + 2]; // lower_bound(idx >= j), j in [0, N+1]

// ---------------------------------------------------------------------------
// Kernel 1: z = x @ w, a = sigmoid(z).  One warp per row. The 8 row loads are
// issued as back-to-back volatile asm LDG.128 so ptxas cannot re-serialize
// them (R6 failure mode): per-warp MLP 1 -> 8. Values and FFMA order are
// unchanged -> g_a bitwise identical to the validated kernel.
// ---------------------------------------------------------------------------
__global__ void __launch_bounds__(256) k_logits(const float* __restrict__ x,
                                                const float* __restrict__ w) {
    const int warp = threadIdx.x >> 5;
    const int lane = threadIdx.x & 31;
    const int row  = blockIdx.x * 8 + warp;

    const float4* xr = reinterpret_cast<const float4*>(x) + (size_t)row * (D / 4);
    const float4* w4 = reinterpret_cast<const float4*>(w);

    // 8 independent LDG.128, force-batched via volatile asm
    float4 xv[8];
#pragma unroll
    for (int k = 0; k < 8; k++) {
        asm volatile("ld.global.nc.v4.f32 {%0,%1,%2,%3}, [%4];"
                     : "=f"(xv[k].x), "=f"(xv[k].y), "=f"(xv[k].z), "=f"(xv[k].w)
                     : "l"(xr + lane + 32 * k));
    }

    float s = 0.f;
#pragma unroll
    for (int k = 0; k < 8; k++) {
        const float4 wv = __ldg(&w4[lane + 32 * k]);
        s += xv[k].x * wv.x;
        s += xv[k].y * wv.y;
        s += xv[k].z * wv.z;
        s += xv[k].w * wv.w;
    }
#pragma unroll
    for (int off = 16; off; off >>= 1)
        s += __shfl_xor_sync(0xffffffffu, s, off);

    if (lane == 0) {
        float z = s, a;
        if (z >= 0.f) {
            a = 1.f / (1.f + expf(-z));
        } else {
            float e = expf(z);
            a = e / (1.f + e);
        }
        g_a[row] = a;
    }
}

// ---------------------------------------------------------------------------
// Kernel 2: b = cumsum(a) replicating jax.lax.associative_scan's fp32 tree,
// then derive per-column {idx, m, c} and the exact rowstart table.
// idx is non-decreasing with steps <= 1 (a_i < 1): crossing thread writes
// rowstart directly, no atomics, no search.  (Unchanged from R9.)
// ---------------------------------------------------------------------------
__global__ void k_scan() {
    __shared__ float sh[8192];
    const int tid = threadIdx.x;   // 1024 threads

    for (int i = tid; i < 4096; i += 1024)
        sh[i] = g_a[2 * i] + g_a[2 * i + 1];
    __syncthreads();
    for (int l = 2; l <= 7; l++) {                 // n = 2048 .. 64
        const int n    = N >> l;
        const int off  = 8192 - 2 * (8192 >> l);
        const int offp = 8192 - 2 * (8192 >> (l - 1));
        for (int i = tid; i < n; i += 1024)
            sh[off + i] = sh[offp + 2 * i] + sh[offp + 2 * i + 1];
        __syncthreads();
    }

    if (tid < 32) {
        for (int l = 8; l <= 13; l++) {
            const int n    = N >> l;
            const int off  = 8192 - 2 * (8192 >> l);
            const int offp = 8192 - 2 * (8192 >> (l - 1));
            if (tid < n)
                sh[off + tid] = sh[offp + 2 * tid] + sh[offp + 2 * tid + 1];
            __syncwarp();
        }
        for (int l = 12; l >= 8; l--) {
            const int n    = N >> l;
            const int off  = 8192 - 2 * (8192 >> l);
            const int offc = 8192 - 2 * (8192 >> (l + 1));
            float v = 0.f;
            if (tid < n) {
                if (tid & 1)       v = sh[offc + (tid >> 1)];
                else if (tid == 0) v = sh[off];
                else               v = sh[offc + (tid >> 1) - 1] + sh[off + tid];
            }
            __syncwarp();
            if (tid < n) sh[off + tid] = v;
            __syncwarp();
        }
    }
    __syncthreads();

    for (int l = 7; l >= 1; l--) {                 // n = 64 .. 4096, in place
        const int n    = N >> l;
        const int off  = 8192 - 2 * (8192 >> l);
        const int offc = 8192 - 2 * (8192 >> (l + 1));
        for (int i = tid; i < n; i += 1024) {
            float v;
            if (i & 1)       v = sh[offc + (i >> 1)];
            else if (i == 0) v = sh[off];
            else             v = sh[offc + (i >> 1) - 1] + sh[off + i];
            sh[off + i] = v;
        }
        __syncthreads();
    }

    int last_idx = 0;
    for (int i = tid; i < N; i += 1024) {
        const float ai = g_a[i];
        float bi;
        if (i == 0)      bi = ai;
        else if (i & 1)  bi = sh[i >> 1];
        else             bi = sh[(i >> 1) - 1] + ai;

        int prev;
        if (i == 0) {
            prev = 0;
        } else {
            const int k = i - 1;
            float bp;
            if (k == 0)      bp = g_a[0];
            else if (k & 1)  bp = sh[k >> 1];
            else             bp = sh[(k >> 1) - 1] + g_a[k];
            prev = (int)floorf(bp);
        }
        const int idx   = (int)floorf(bi);
        const bool same = (idx == prev);
        const float frac = bi - (float)idx;

        const float m = same ? ai : frac;
        const float c = same ? 0.f : (ai - frac);
        g_pack[i] = make_int4(idx, __float_as_int(m), __float_as_int(c), 0);

        if (i == 0) g_rowstart[0] = 0;
        else if (!same) g_rowstart[idx] = i;
        if (i == N - 1) last_idx = idx;
    }
    __syncthreads();

    __shared__ int s_last;
    if (tid == ((N - 1) & 1023)) s_last = last_idx;
    __syncthreads();
    for (int j = s_last + 1 + tid; j <= N + 1; j += 1024)
        g_rowstart[j] = N;
}

// ---------------------------------------------------------------------------
// Kernel 3: gather (R9, unchanged — best known). One block per output row;
// span [rowstart[j], rowstart[j+2]); lane-parallel pack prefetch + shfl
// broadcast; |w| <= 1e-12 contributions skipped (validated sub-tolerance).
// ---------------------------------------------------------------------------
__global__ void __launch_bounds__(256) k_gather(const float* __restrict__ x,
                                                float* __restrict__ out) {
    const int j = blockIdx.x;     // output row
    const int t = threadIdx.x;    // 0..255, float4 lanes
    const int lane = t & 31;

    const int s = __ldg(&g_rowstart[j]);
    const int e = __ldg(&g_rowstart[j + 2]);

    float4 acc = make_float4(0.f, 0.f, 0.f, 0.f);
    for (int base = s; base < e; base += 32) {
        float wl = 0.f;
        const int i = base + lane;
        if (i < e) {
            const int4 p = __ldg(&g_pack[i]);
            if (p.x == j)          wl = __int_as_float(p.y);   // m
            else if (p.x == j + 1) wl = __int_as_float(p.z);   // c
        }
        const int cnt = min(32, e - base);
#pragma unroll 4
        for (int k = 0; k < cnt; k++) {
            const float wk = __shfl_sync(0xffffffffu, wl, k);
            if (fabsf(wk) > 1e-12f) {   // warp-uniform; sub-tolerance skip
                const float4 v =
                    reinterpret_cast<const float4*>(x)[(size_t)(base + k) * (D / 4) + t];
                acc.x += wk * v.x;
                acc.y += wk * v.y;
                acc.z += wk * v.z;
                acc.w += wk * v.w;
            }
        }
    }
    reinterpret_cast<float4*>(out)[(size_t)j * (D / 4) + t] = acc;
}

// ---------------------------------------------------------------------------
extern "C" void kernel_launch(void* const* d_in, const int* in_sizes, int n_in,
                              void* d_out, int out_size) {
    const float* x = (const float*)d_in[0];   // [8192, 1024] f32
    const float* w = (const float*)d_in[1];   // [1024, 1]    f32
    float* out = (float*)d_out;               // [8192, 1024] f32

    k_logits<<<N / 8, 256>>>(x, w);
    k_scan<<<1, 1024>>>();
    k_gather<<<N, 256>>>(x, out);
}